// round 3
// baseline (speedup 1.0000x reference)
#include <cuda_runtime.h>
#include <math.h>

#define BB     256
#define MEMN   70
#define SLENQ  11
#define LQ     71
#define BL     (BB*LQ)       // 18176
#define HD     512
#define FSZ    2048
#define NHEAD  8
#define DKH    64
#define NLMAX  6
#define VOC    32000
#define THRESHV 0.9f
#define EPSV   1e-6f

// ---------------- scratch (device globals; no allocation) ----------------
__device__ float g_x[BL*HD];
__device__ float g_state[BL*HD];
__device__ float g_prev[BL*HD];
__device__ float g_s[BL*HD];
__device__ float g_xn[BL*HD];
__device__ float g_q[BL*HD];
__device__ float g_k[BL*HD];
__device__ float g_v[BL*HD];
__device__ float g_ctx[BL*HD];
__device__ float g_s2[BL*HD];
__device__ float g_xn2[BL*HD];
__device__ float g_y[BL*HD];
__device__ float g_mid[BL*FSZ];          // 149 MB
__device__ float g_w1t[3*HD*FSZ];        // [3*512][2048]
__device__ float g_w2t[3*FSZ*HD];        // [3*2048][512]
__device__ float g_tsig[LQ*HD];
__device__ float g_psig[NLMAX*HD];
__device__ float g_hp[BL], g_rem[BL], g_nu[BL], g_pr[BL];
__device__ float g_pooled[BB*HD];
__device__ int   g_active;

// ---------------- reductions ----------------
__device__ __forceinline__ float blockReduceSum(float v) {
    __shared__ float sh[32];
    __shared__ float res;
    int lane = threadIdx.x & 31, wid = threadIdx.x >> 5;
#pragma unroll
    for (int o = 16; o; o >>= 1) v += __shfl_xor_sync(0xffffffffu, v, o);
    if (lane == 0) sh[wid] = v;
    __syncthreads();
    if (wid == 0) {
        float x = (lane < (int)(blockDim.x >> 5)) ? sh[lane] : 0.f;
#pragma unroll
        for (int o = 16; o; o >>= 1) x += __shfl_xor_sync(0xffffffffu, x, o);
        if (lane == 0) res = x;
    }
    __syncthreads();
    return res;
}

__device__ __forceinline__ float blockReduceMax(float v) {
    __shared__ float sh[32];
    __shared__ float res;
    int lane = threadIdx.x & 31, wid = threadIdx.x >> 5;
#pragma unroll
    for (int o = 16; o; o >>= 1) v = fmaxf(v, __shfl_xor_sync(0xffffffffu, v, o));
    if (lane == 0) sh[wid] = v;
    __syncthreads();
    if (wid == 0) {
        float x = (lane < (int)(blockDim.x >> 5)) ? sh[lane] : -3.0e38f;
#pragma unroll
        for (int o = 16; o; o >>= 1) x = fmaxf(x, __shfl_xor_sync(0xffffffffu, x, o));
        if (lane == 0) res = x;
    }
    __syncthreads();
    return res;
}

// ---------------- init / signals ----------------
__global__ void k_init() {
    int i = blockIdx.x * blockDim.x + threadIdx.x;
    if (i < BL*HD) g_prev[i] = 0.f;
    if (i < BL) { g_hp[i] = 0.f; g_rem[i] = 0.f; g_nu[i] = 0.f; }
}

__global__ void k_sigs() {
    int i = blockIdx.x * blockDim.x + threadIdx.x;
    const float log_inc = logf(1e4f) / 255.f;
    if (i < LQ*HD) {
        int pos = i / HD, c = i % HD;
        int j = (c < 256) ? c : c - 256;
        float val = (float)pos * expf(-log_inc * (float)j);
        g_tsig[i] = (c < 256) ? sinf(val) : cosf(val);
    } else {
        int k = i - LQ*HD;
        if (k < NLMAX*HD) {
            int pos = k / HD, c = k % HD;
            int j = (c < 256) ? c : c - 256;
            float val = (float)pos * expf(-log_inc * (float)j);
            g_psig[k] = (c < 256) ? sinf(val) : cosf(val);
        }
    }
}

// c1_w [2048][512][3] -> g_w1t[kk*512+c][2048]
__global__ void k_wt1(const float* __restrict__ w) {
    int i = blockIdx.x * blockDim.x + threadIdx.x;
    if (i < 3*HD*FSZ) {
        int f = i % FSZ;
        int rest = i / FSZ;         // kk*512 + c
        int kk = rest / HD, c = rest % HD;
        g_w1t[i] = w[(f*HD + c)*3 + kk];
    }
}

// c2_w [512][2048][3] -> g_w2t[kk*2048+c][512]
__global__ void k_wt2(const float* __restrict__ w) {
    int i = blockIdx.x * blockDim.x + threadIdx.x;
    if (i < 3*FSZ*HD) {
        int f = i % HD;
        int rest = i / HD;          // kk*2048 + c
        int kk = rest / FSZ, c = rest % FSZ;
        g_w2t[i] = w[(f*FSZ + c)*3 + kk];
    }
}

// ---------------- embedding ----------------
__global__ void k_embed(const int* __restrict__ story, const int* __restrict__ query,
                        const float* __restrict__ emb, const float* __restrict__ mask) {
    int row = blockIdx.x;            // b*LQ + m
    int b = row / LQ, m = row % LQ;
    for (int c = threadIdx.x; c < HD; c += blockDim.x) {
        float acc = 0.f;
        if (m < MEMN) {
#pragma unroll
            for (int s = 0; s < SLENQ; s++) {
                int tok = story[(b*MEMN + m)*SLENQ + s];
                acc += emb[(long)tok*HD + c] * mask[s*HD + c];
            }
        } else {
#pragma unroll
            for (int s = 0; s < SLENQ; s++) {
                int tok = query[b*SLENQ + s];
                acc += emb[(long)tok*HD + c] * mask[s*HD + c];
            }
        }
        g_x[row*HD + c] = acc;
    }
}

// ---------------- generic tiled SGEMM (NN): C = act(scale*A@W + bias + resid) ----------------
__global__ void k_gemm(const float* __restrict__ A, const float* __restrict__ W,
                       float* __restrict__ C, int M, int N, int K,
                       const float* __restrict__ bias, const float* __restrict__ resid,
                       float scale, int relu, int chk) {
    if (chk && !g_active) return;
    __shared__ float As[16][65];
    __shared__ float Bs[16][64];
    int n0 = blockIdx.x * 64, m0 = blockIdx.y * 64;
    int tid = threadIdx.x;
    int tx = tid & 15, ty = tid >> 4;
    float acc[4][4];
#pragma unroll
    for (int i = 0; i < 4; i++)
#pragma unroll
        for (int j = 0; j < 4; j++) acc[i][j] = 0.f;

    for (int k0 = 0; k0 < K; k0 += 16) {
#pragma unroll
        for (int i = 0; i < 4; i++) {
            int idx = tid + i*256;
            int kl = idx & 15, ml = idx >> 4;
            As[kl][ml] = A[(m0 + ml)*K + k0 + kl];
        }
#pragma unroll
        for (int i = 0; i < 4; i++) {
            int idx = tid + i*256;
            int nl = idx & 63, kl = idx >> 6;
            Bs[kl][nl] = W[(k0 + kl)*N + n0 + nl];
        }
        __syncthreads();
#pragma unroll
        for (int k = 0; k < 16; k++) {
            float a[4], b[4];
#pragma unroll
            for (int i = 0; i < 4; i++) a[i] = As[k][ty*4 + i];
#pragma unroll
            for (int j = 0; j < 4; j++) b[j] = Bs[k][tx*4 + j];
#pragma unroll
            for (int i = 0; i < 4; i++)
#pragma unroll
                for (int j = 0; j < 4; j++) acc[i][j] += a[i]*b[j];
        }
        __syncthreads();
    }
#pragma unroll
    for (int i = 0; i < 4; i++) {
        int m = m0 + ty*4 + i;
#pragma unroll
        for (int j = 0; j < 4; j++) {
            int n = n0 + tx*4 + j;
            float v = acc[i][j]*scale;
            if (bias)  v += bias[n];
            if (resid) v += resid[m*N + n];
            if (relu)  v = fmaxf(v, 0.f);
            C[m*N + n] = v;
        }
    }
}

// ---------------- im2col conv GEMM: K' = 3*Cin, A gathered with l-shift ----------------
__global__ void k_convgemm(const float* __restrict__ X, const float* __restrict__ Wt,
                           float* __restrict__ C, int N, int Cin, int cshift,
                           const float* __restrict__ bias, const float* __restrict__ resid,
                           int relu) {
    if (!g_active) return;
    __shared__ float As[16][65];
    __shared__ float Bs[16][64];
    int n0 = blockIdx.x * 64, m0 = blockIdx.y * 64;
    int Kp = 3*Cin;
    int tid = threadIdx.x;
    int tx = tid & 15, ty = tid >> 4;
    float acc[4][4];
#pragma unroll
    for (int i = 0; i < 4; i++)
#pragma unroll
        for (int j = 0; j < 4; j++) acc[i][j] = 0.f;

    for (int k0 = 0; k0 < Kp; k0 += 16) {
        int kk = k0 >> cshift;             // K-tile never straddles a Cin boundary
        int cbase = k0 & (Cin - 1);
#pragma unroll
        for (int i = 0; i < 4; i++) {
            int idx = tid + i*256;
            int kl = idx & 15, ml = idx >> 4;
            int m = m0 + ml;
            int b = m / LQ, l = m - b*LQ;
            int lp = l + kk - 1;
            float val = 0.f;
            if (lp >= 0 && lp < LQ) val = X[(b*LQ + lp)*Cin + cbase + kl];
            As[kl][ml] = val;
        }
#pragma unroll
        for (int i = 0; i < 4; i++) {
            int idx = tid + i*256;
            int nl = idx & 63, kl = idx >> 6;
            Bs[kl][nl] = Wt[(k0 + kl)*N + n0 + nl];
        }
        __syncthreads();
#pragma unroll
        for (int k = 0; k < 16; k++) {
            float a[4], b[4];
#pragma unroll
            for (int i = 0; i < 4; i++) a[i] = As[k][ty*4 + i];
#pragma unroll
            for (int j = 0; j < 4; j++) b[j] = Bs[k][tx*4 + j];
#pragma unroll
            for (int i = 0; i < 4; i++)
#pragma unroll
                for (int j = 0; j < 4; j++) acc[i][j] += a[i]*b[j];
        }
        __syncthreads();
    }
#pragma unroll
    for (int i = 0; i < 4; i++) {
        int m = m0 + ty*4 + i;
#pragma unroll
        for (int j = 0; j < 4; j++) {
            int n = n0 + tx*4 + j;
            float v = acc[i][j];
            if (bias)  v += bias[n];
            if (resid) v += resid[m*N + n];
            if (relu)  v = fmaxf(v, 0.f);
            C[m*N + n] = v;
        }
    }
}

// ---------------- GEMM NT for output: C[m,n] = A[m,:]·Bt[n,:] + bias[n] ----------------
__global__ void k_gemm_nt(const float* __restrict__ A, const float* __restrict__ Bt,
                          const float* __restrict__ bias, float* __restrict__ C,
                          int M, int N, int K) {
    __shared__ float As[16][65];
    __shared__ float Bs[16][65];
    int n0 = blockIdx.x * 64, m0 = blockIdx.y * 64;
    int tid = threadIdx.x;
    int tx = tid & 15, ty = tid >> 4;
    float acc[4][4];
#pragma unroll
    for (int i = 0; i < 4; i++)
#pragma unroll
        for (int j = 0; j < 4; j++) acc[i][j] = 0.f;

    for (int k0 = 0; k0 < K; k0 += 16) {
#pragma unroll
        for (int i = 0; i < 4; i++) {
            int idx = tid + i*256;
            int kl = idx & 15, ml = idx >> 4;
            As[kl][ml] = A[(m0 + ml)*K + k0 + kl];
        }
#pragma unroll
        for (int i = 0; i < 4; i++) {
            int idx = tid + i*256;
            int kl = idx & 15, nl = idx >> 4;
            Bs[kl][nl] = Bt[(long)(n0 + nl)*K + k0 + kl];
        }
        __syncthreads();
#pragma unroll
        for (int k = 0; k < 16; k++) {
            float a[4], b[4];
#pragma unroll
            for (int i = 0; i < 4; i++) a[i] = As[k][ty*4 + i];
#pragma unroll
            for (int j = 0; j < 4; j++) b[j] = Bs[k][tx*4 + j];
#pragma unroll
            for (int i = 0; i < 4; i++)
#pragma unroll
                for (int j = 0; j < 4; j++) acc[i][j] += a[i]*b[j];
        }
        __syncthreads();
    }
#pragma unroll
    for (int i = 0; i < 4; i++) {
        int m = m0 + ty*4 + i;
#pragma unroll
        for (int j = 0; j < 4; j++) {
            int n = n0 + tx*4 + j;
            C[(long)m*N + n] = acc[i][j] + bias[n];
        }
    }
}

// ---------------- ACT step pieces ----------------
__global__ void k_active_chk() {
    __shared__ int any;
    if (threadIdx.x == 0) any = 0;
    __syncthreads();
    int loc = 0;
    for (int i = threadIdx.x; i < BL; i += blockDim.x)
        if (g_hp[i] < THRESHV && g_nu[i] < (float)NLMAX) loc = 1;
    if (loc) atomicOr(&any, 1);
    __syncthreads();
    if (threadIdx.x == 0) g_active = any;
}

__global__ void k_builds(int t, const float* __restrict__ pw, const float* __restrict__ pb) {
    if (!g_active) return;
    int row = blockIdx.x;
    int l = row % LQ;
    float dot = 0.f;
    for (int c = threadIdx.x; c < HD; c += blockDim.x) {
        float v = g_state[row*HD + c] + g_tsig[l*HD + c] + g_psig[t*HD + c];
        g_s[row*HD + c] = v;
        dot += v * pw[c];
    }
    float tot = blockReduceSum(dot);
    if (threadIdx.x == 0)
        g_pr[row] = 1.f / (1.f + expf(-(tot + pb[0])));
}

__global__ void k_ln(const float* __restrict__ X, const float* __restrict__ g,
                     const float* __restrict__ b, float* __restrict__ Y) {
    if (!g_active) return;
    int row = blockIdx.x;
    const float* x = X + row*HD;
    float s = 0.f;
    for (int c = threadIdx.x; c < HD; c += blockDim.x) s += x[c];
    float mu = blockReduceSum(s) / (float)HD;
    float vs = 0.f;
    for (int c = threadIdx.x; c < HD; c += blockDim.x) {
        float d = x[c] - mu; vs += d*d;
    }
    float var = blockReduceSum(vs) / (float)(HD - 1);
    float inv = 1.f / (sqrtf(var) + EPSV);
    for (int c = threadIdx.x; c < HD; c += blockDim.x)
        Y[row*HD + c] = g[c]*(x[c] - mu)*inv + b[c];
}

__global__ void k_attn() {
    if (!g_active) return;
    int bh = blockIdx.x;
    int b = bh / NHEAD, h = bh % NHEAD;
    __shared__ float ks[LQ*65];
    __shared__ float vs[LQ*65];
    __shared__ float qrow[4][DKH];
    __shared__ float ps[4][LQ + 1];
    int tid = threadIdx.x;
    long base = (long)(b*LQ)*HD + h*DKH;
    for (int i = tid; i < LQ*DKH; i += 128) {
        int j = i / DKH, d = i % DKH;
        ks[j*65 + d] = g_k[base + (long)j*HD + d];
        vs[j*65 + d] = g_v[base + (long)j*HD + d];
    }
    __syncthreads();
    int w = tid >> 5, lane = tid & 31;
    for (int r = w; r < LQ; r += 4) {
        for (int d = lane; d < DKH; d += 32) qrow[w][d] = g_q[base + (long)r*HD + d];
        __syncwarp();
        float sc[3];
#pragma unroll
        for (int jj = 0; jj < 3; jj++) {
            int j = lane + jj*32;
            float a = -3.0e38f;
            if (j < LQ) {
                a = 0.f;
#pragma unroll
                for (int d = 0; d < DKH; d++) a += qrow[w][d]*ks[j*65 + d];
            }
            sc[jj] = a;
        }
        float mx = fmaxf(sc[0], fmaxf(sc[1], sc[2]));
#pragma unroll
        for (int o = 16; o; o >>= 1) mx = fmaxf(mx, __shfl_xor_sync(0xffffffffu, mx, o));
        float sum = 0.f;
#pragma unroll
        for (int jj = 0; jj < 3; jj++) {
            int j = lane + jj*32;
            float e = (j < LQ) ? expf(sc[jj] - mx) : 0.f;
            sc[jj] = e; sum += e;
        }
#pragma unroll
        for (int o = 16; o; o >>= 1) sum += __shfl_xor_sync(0xffffffffu, sum, o);
        float inv = 1.f / sum;
#pragma unroll
        for (int jj = 0; jj < 3; jj++) {
            int j = lane + jj*32;
            if (j < LQ) ps[w][j] = sc[jj]*inv;
        }
        __syncwarp();
        for (int d = lane; d < DKH; d += 32) {
            float a = 0.f;
#pragma unroll 8
            for (int j = 0; j < LQ; j++) a += ps[w][j]*vs[j*65 + d];
            g_ctx[base + (long)r*HD + d] = a;
        }
        __syncwarp();
    }
}

__global__ void k_halt() {
    if (!g_active) return;
    int row = blockIdx.x;
    __shared__ float s_uw;
    if (threadIdx.x == 0) {
        float pr = g_pr[row], hp = g_hp[row], rem = g_rem[row], nu = g_nu[row];
        float still = (hp < 1.0f) ? 1.f : 0.f;
        float tot = hp + pr*still;
        float nh  = ((tot > THRESHV) ? 1.f : 0.f)*still;
        float st2 = ((tot <= THRESHV) ? 1.f : 0.f)*still;
        float hp2 = hp + pr*st2;
        float rem2 = rem + nh*(1.f - hp2);
        hp2 = hp2 + nh*rem2;
        float nu2 = nu + st2 + nh;
        float uw = pr*st2 + nh*rem2;
        g_hp[row] = hp2; g_rem[row] = rem2; g_nu[row] = nu2;
        s_uw = uw;
    }
    __syncthreads();
    float uw = s_uw;
    for (int c = threadIdx.x; c < HD; c += blockDim.x) {
        int i = row*HD + c;
        float y = g_y[i];
        g_prev[i]  = y*uw + g_prev[i]*(1.f - uw);
        g_state[i] = y;
    }
}

// ---------------- pooling / softmax / tail ----------------
__global__ void k_pool() {
    int b = blockIdx.x;
    for (int c = threadIdx.x; c < HD; c += blockDim.x) {
        float a = 0.f;
        for (int l = 0; l < LQ; l++) a += g_prev[(b*LQ + l)*HD + c];
        g_pooled[b*HD + c] = a / (float)LQ;
    }
}

__global__ void k_softmax(float* __restrict__ out) {
    int b = blockIdx.x;
    const float* a = out + (long)b*VOC;
    float* sm = out + (long)BB*VOC + (long)b*VOC;
    float mx = -3.0e38f;
    for (int i = threadIdx.x; i < VOC; i += blockDim.x) mx = fmaxf(mx, a[i]);
    float M = blockReduceMax(mx);
    float s = 0.f;
    for (int i = threadIdx.x; i < VOC; i += blockDim.x) s += expf(a[i] - M);
    float S = blockReduceSum(s);
    float inv = 1.f / S;
    for (int i = threadIdx.x; i < VOC; i += blockDim.x) sm[i] = expf(a[i] - M)*inv;
}

__global__ void k_tail(float* __restrict__ out) {
    int i = blockIdx.x * blockDim.x + threadIdx.x;
    if (i < BL) {
        out[(long)2*BB*VOC + i]      = g_rem[i];
        out[(long)2*BB*VOC + BL + i] = g_nu[i];
    }
}

// ---------------- host ----------------
extern "C" void kernel_launch(void* const* d_in, const int* in_sizes, int n_in,
                              void* d_out, int out_size) {
    const int*   story = (const int*)d_in[0];
    const int*   query = (const int*)d_in[1];
    const float* emb   = (const float*)d_in[2];
    const float* mask  = (const float*)d_in[3];
    const float* projw = (const float*)d_in[4];
    const float* ln1g  = (const float*)d_in[5];
    const float* ln1b  = (const float*)d_in[6];
    const float* wq    = (const float*)d_in[7];
    const float* wk    = (const float*)d_in[8];
    const float* wv    = (const float*)d_in[9];
    const float* wo    = (const float*)d_in[10];
    const float* c1w   = (const float*)d_in[11];
    const float* c1b   = (const float*)d_in[12];
    const float* c2w   = (const float*)d_in[13];
    const float* c2b   = (const float*)d_in[14];
    const float* ln2g  = (const float*)d_in[15];
    const float* ln2b  = (const float*)d_in[16];
    const float* pw    = (const float*)d_in[17];
    const float* pb    = (const float*)d_in[18];
    const float* outb  = (const float*)d_in[19];
    float* out = (float*)d_out;

    void *p_x, *p_state, *p_s, *p_xn, *p_q, *p_k, *p_v, *p_ctx, *p_s2, *p_xn2,
         *p_y, *p_mid, *p_w1t, *p_w2t, *p_pooled;
    cudaGetSymbolAddress(&p_x, g_x);
    cudaGetSymbolAddress(&p_state, g_state);
    cudaGetSymbolAddress(&p_s, g_s);
    cudaGetSymbolAddress(&p_xn, g_xn);
    cudaGetSymbolAddress(&p_q, g_q);
    cudaGetSymbolAddress(&p_k, g_k);
    cudaGetSymbolAddress(&p_v, g_v);
    cudaGetSymbolAddress(&p_ctx, g_ctx);
    cudaGetSymbolAddress(&p_s2, g_s2);
    cudaGetSymbolAddress(&p_xn2, g_xn2);
    cudaGetSymbolAddress(&p_y, g_y);
    cudaGetSymbolAddress(&p_mid, g_mid);
    cudaGetSymbolAddress(&p_w1t, g_w1t);
    cudaGetSymbolAddress(&p_w2t, g_w2t);
    cudaGetSymbolAddress(&p_pooled, g_pooled);

    k_sigs<<<(LQ*HD + NLMAX*HD + 255)/256, 256>>>();
    k_wt1<<<(3*HD*FSZ + 255)/256, 256>>>(c1w);
    k_wt2<<<(3*FSZ*HD + 255)/256, 256>>>(c2w);
    k_init<<<(BL*HD + 255)/256, 256>>>();
    k_embed<<<BL, 128>>>(story, query, emb, mask);

    // state = x @ proj_w
    {
        dim3 grid(HD/64, BL/64);
        k_gemm<<<grid, 256>>>((const float*)p_x, projw, (float*)p_state,
                              BL, HD, HD, nullptr, nullptr, 1.f, 0, 0);
    }

    for (int t = 0; t < NLMAX; t++) {
        k_active_chk<<<1, 1024>>>();
        k_builds<<<BL, 256>>>(t, pw, pb);
        k_ln<<<BL, 256>>>((const float*)p_s, ln1g, ln1b, (float*)p_xn);
        dim3 g512(HD/64, BL/64);
        k_gemm<<<g512, 256>>>((const float*)p_xn, wq, (float*)p_q, BL, HD, HD,
                              nullptr, nullptr, 0.125f, 0, 1);
        k_gemm<<<g512, 256>>>((const float*)p_xn, wk, (float*)p_k, BL, HD, HD,
                              nullptr, nullptr, 1.f, 0, 1);
        k_gemm<<<g512, 256>>>((const float*)p_xn, wv, (float*)p_v, BL, HD, HD,
                              nullptr, nullptr, 1.f, 0, 1);
        k_attn<<<BB*NHEAD, 128>>>();
        k_gemm<<<g512, 256>>>((const float*)p_ctx, wo, (float*)p_s2, BL, HD, HD,
                              nullptr, (const float*)p_s, 1.f, 0, 1);
        k_ln<<<BL, 256>>>((const float*)p_s2, ln2g, ln2b, (float*)p_xn2);
        dim3 gc1(FSZ/64, BL/64);
        k_convgemm<<<gc1, 256>>>((const float*)p_xn2, (const float*)p_w1t, (float*)p_mid,
                                 FSZ, HD, 9, c1b, nullptr, 1);
        dim3 gc2(HD/64, BL/64);
        k_convgemm<<<gc2, 256>>>((const float*)p_mid, (const float*)p_w2t, (float*)p_y,
                                 HD, FSZ, 11, c2b, (const float*)p_s2, 0);
        k_halt<<<BL, 256>>>();
    }

    k_pool<<<BB, 256>>>();
    {
        dim3 grid(VOC/64, BB/64);
        k_gemm_nt<<<grid, 256>>>((const float*)p_pooled, emb, outb, out, BB, VOC, HD);
    }
    k_softmax<<<BB, 1024>>>(out);
    k_tail<<<(BL + 255)/256, 256>>>(out);
}

// round 5
// speedup vs baseline: 2.5057x; 2.5057x over previous
#include <cuda_runtime.h>
#include <math.h>

#define BB     256
#define MEMN   70
#define SLENQ  11
#define LQ     71
#define BL     (BB*LQ)       // 18176
#define HD     512
#define FSZ    2048
#define NHEAD  8
#define DKH    64
#define NLMAX  6
#define VOC    32000
#define THRESHV 0.9f
#define EPSV   1e-6f

#define SMEM_BYTES 73728     // 2*128*36*4 (A) + 2*128*36*4 (B, NT worst case)

// ---------------- scratch (device globals; no allocation) ----------------
__device__ float g_x[BL*HD];
__device__ float g_state[BL*HD];
__device__ float g_prev[BL*HD];
__device__ float g_s[BL*HD];
__device__ float g_xn[BL*HD];
__device__ float g_q[BL*HD];
__device__ float g_k[BL*HD];
__device__ float g_v[BL*HD];
__device__ float g_ctx[BL*HD];
__device__ float g_s2[BL*HD];
__device__ float g_xn2[BL*HD];
__device__ float g_y[BL*HD];
__device__ float g_mid[BL*FSZ];
__device__ float g_w1t[3*HD*FSZ];        // [3*512][2048]
__device__ float g_w2t[3*FSZ*HD];        // [3*2048][512]
__device__ float g_tsig[LQ*HD];
__device__ float g_psig[NLMAX*HD];
__device__ float g_hp[BL], g_rem[BL], g_nu[BL], g_pr[BL];
__device__ float g_pooled[BB*HD];
__device__ int   g_active;

// ---------------- helpers ----------------
__device__ __forceinline__ unsigned f2tf(float f) {
    unsigned u;
    asm("cvt.rna.tf32.f32 %0, %1;" : "=r"(u) : "f"(f));
    return u;
}

__device__ __forceinline__ void mma_tf32(float* d, const unsigned* a, const unsigned* b) {
    asm volatile(
        "mma.sync.aligned.m16n8k8.row.col.f32.tf32.tf32.f32 "
        "{%0,%1,%2,%3}, {%4,%5,%6,%7}, {%8,%9}, {%0,%1,%2,%3};"
        : "+f"(d[0]), "+f"(d[1]), "+f"(d[2]), "+f"(d[3])
        : "r"(a[0]), "r"(a[1]), "r"(a[2]), "r"(a[3]), "r"(b[0]), "r"(b[1]));
}

__device__ __forceinline__ float blockReduceSum(float v) {
    __shared__ float sh[32];
    __shared__ float res;
    int lane = threadIdx.x & 31, wid = threadIdx.x >> 5;
#pragma unroll
    for (int o = 16; o; o >>= 1) v += __shfl_xor_sync(0xffffffffu, v, o);
    if (lane == 0) sh[wid] = v;
    __syncthreads();
    if (wid == 0) {
        float x = (lane < (int)(blockDim.x >> 5)) ? sh[lane] : 0.f;
#pragma unroll
        for (int o = 16; o; o >>= 1) x += __shfl_xor_sync(0xffffffffu, x, o);
        if (lane == 0) res = x;
    }
    __syncthreads();
    return res;
}

__device__ __forceinline__ float blockReduceMax(float v) {
    __shared__ float sh[32];
    __shared__ float res;
    int lane = threadIdx.x & 31, wid = threadIdx.x >> 5;
#pragma unroll
    for (int o = 16; o; o >>= 1) v = fmaxf(v, __shfl_xor_sync(0xffffffffu, v, o));
    if (lane == 0) sh[wid] = v;
    __syncthreads();
    if (wid == 0) {
        float x = (lane < (int)(blockDim.x >> 5)) ? sh[lane] : -3.0e38f;
#pragma unroll
        for (int o = 16; o; o >>= 1) x = fmaxf(x, __shfl_xor_sync(0xffffffffu, x, o));
        if (lane == 0) res = x;
    }
    __syncthreads();
    return res;
}

// ---------------- init / signals / weight transpose ----------------
__global__ void k_init() {
    int i = blockIdx.x * blockDim.x + threadIdx.x;
    if (i < BL*HD) g_prev[i] = 0.f;
    if (i < BL) { g_hp[i] = 0.f; g_rem[i] = 0.f; g_nu[i] = 0.f; }
}

__global__ void k_sigs() {
    int i = blockIdx.x * blockDim.x + threadIdx.x;
    const float log_inc = logf(1e4f) / 255.f;
    if (i < LQ*HD) {
        int pos = i / HD, c = i % HD;
        int j = (c < 256) ? c : c - 256;
        float val = (float)pos * expf(-log_inc * (float)j);
        g_tsig[i] = (c < 256) ? sinf(val) : cosf(val);
    } else {
        int k = i - LQ*HD;
        if (k < NLMAX*HD) {
            int pos = k / HD, c = k % HD;
            int j = (c < 256) ? c : c - 256;
            float val = (float)pos * expf(-log_inc * (float)j);
            g_psig[k] = (c < 256) ? sinf(val) : cosf(val);
        }
    }
}

__global__ void k_wt1(const float* __restrict__ w) {
    int i = blockIdx.x * blockDim.x + threadIdx.x;
    if (i < 3*HD*FSZ) {
        int f = i % FSZ;
        int rest = i / FSZ;
        int kk = rest / HD, c = rest % HD;
        g_w1t[i] = w[(f*HD + c)*3 + kk];
    }
}

__global__ void k_wt2(const float* __restrict__ w) {
    int i = blockIdx.x * blockDim.x + threadIdx.x;
    if (i < 3*FSZ*HD) {
        int f = i % HD;
        int rest = i / HD;
        int kk = rest / FSZ, c = rest % FSZ;
        g_w2t[i] = w[(f*FSZ + c)*3 + kk];
    }
}

// ---------------- embedding ----------------
__global__ void k_embed(const int* __restrict__ story, const int* __restrict__ query,
                        const float* __restrict__ emb, const float* __restrict__ mask) {
    int row = blockIdx.x;
    int b = row / LQ, m = row % LQ;
    for (int c = threadIdx.x; c < HD; c += blockDim.x) {
        float acc = 0.f;
        if (m < MEMN) {
#pragma unroll
            for (int s = 0; s < SLENQ; s++) {
                int tok = story[(b*MEMN + m)*SLENQ + s];
                acc += emb[(long)tok*HD + c] * mask[s*HD + c];
            }
        } else {
#pragma unroll
            for (int s = 0; s < SLENQ; s++) {
                int tok = query[b*SLENQ + s];
                acc += emb[(long)tok*HD + c] * mask[s*HD + c];
            }
        }
        g_x[row*HD + c] = acc;
    }
}

// ============ tf32 tensor-core GEMM (NN + conv-im2col): 128x128 tile ============
// C = act(scale * A@W + bias + resid)
// conv!=0: A gathered from X[B,L,Cin] with kernel-pos shift; K = 3*Cin.
__global__ void __launch_bounds__(256)
k_gemm_tc(const float* __restrict__ A, const float* __restrict__ W,
          float* __restrict__ C, int M, int N, int K,
          const float* __restrict__ bias, const float* __restrict__ resid,
          float scale, int relu, int chk, int conv, int Cin, int cshift) {
    if (chk && !g_active) return;
    extern __shared__ float smem[];
    float* AsF = smem;                  // [2][128][36]
    float* BsF = smem + 2*128*36;       // [2][32][132]

    const int tid = threadIdx.x;
    const int m0 = blockIdx.y * 128;
    const int n0 = blockIdx.x * 128;
    const int lane = tid & 31, wid = tid >> 5;
    const int wm = wid & 3, wn = wid >> 2;
    const int g = lane >> 2, t = lane & 3;

    float acc[2][8][4];
#pragma unroll
    for (int mi = 0; mi < 2; mi++)
#pragma unroll
        for (int ni = 0; ni < 8; ni++)
#pragma unroll
            for (int j = 0; j < 4; j++) acc[mi][ni][j] = 0.f;

    float4 areg[4], breg[4];

    const int ar = tid >> 3;            // 0..31
    const int ac4 = (tid & 7) * 4;      // 0..28
    const int br = tid >> 5;            // 0..7
    const int bc4 = (tid & 31) * 4;     // 0..124

    const int NP = K / 32;

    // ---- load panel k0 into registers ----
    auto loadP = [&](int k0) {
        if (conv) {
            int kk = k0 >> cshift;
            int cb = k0 & (Cin - 1);
#pragma unroll
            for (int i = 0; i < 4; i++) {
                int m = m0 + ar + i*32;
                int b = m / LQ, l = m - b*LQ;
                int lp = l + kk - 1;
                if (lp >= 0 && lp < LQ)
                    areg[i] = *(const float4*)&A[(long)(b*LQ + lp)*Cin + cb + ac4];
                else
                    areg[i] = make_float4(0.f, 0.f, 0.f, 0.f);
            }
        } else {
#pragma unroll
            for (int i = 0; i < 4; i++)
                areg[i] = *(const float4*)&A[(long)(m0 + ar + i*32)*K + k0 + ac4];
        }
#pragma unroll
        for (int i = 0; i < 4; i++)
            breg[i] = *(const float4*)&W[(long)(k0 + br + i*8)*N + n0 + bc4];
    };

    auto storeP = [&](int buf) {
        float* As = AsF + buf*128*36;
        float* Bs = BsF + buf*32*132;
#pragma unroll
        for (int i = 0; i < 4; i++) {
            uint4 v;
            v.x = f2tf(areg[i].x); v.y = f2tf(areg[i].y);
            v.z = f2tf(areg[i].z); v.w = f2tf(areg[i].w);
            *(uint4*)&As[(ar + i*32)*36 + ac4] = v;
        }
#pragma unroll
        for (int i = 0; i < 4; i++) {
            uint4 v;
            v.x = f2tf(breg[i].x); v.y = f2tf(breg[i].y);
            v.z = f2tf(breg[i].z); v.w = f2tf(breg[i].w);
            *(uint4*)&Bs[(br + i*8)*132 + bc4] = v;
        }
    };

    auto compute = [&](int buf) {
        const unsigned* As = (const unsigned*)(AsF + buf*128*36);
        const unsigned* Bs = (const unsigned*)(BsF + buf*32*132);
#pragma unroll
        for (int ks = 0; ks < 4; ks++) {
            int kk = ks*8;
            unsigned a[2][4];
#pragma unroll
            for (int mi = 0; mi < 2; mi++) {
                int row = wm*32 + mi*16 + g;
                a[mi][0] = As[row*36 + kk + t];
                a[mi][1] = As[(row + 8)*36 + kk + t];
                a[mi][2] = As[row*36 + kk + t + 4];
                a[mi][3] = As[(row + 8)*36 + kk + t + 4];
            }
            unsigned b[8][2];
#pragma unroll
            for (int ni = 0; ni < 8; ni++) {
                int col = wn*64 + ni*8 + g;
                b[ni][0] = Bs[(kk + t)*132 + col];
                b[ni][1] = Bs[(kk + t + 4)*132 + col];
            }
#pragma unroll
            for (int mi = 0; mi < 2; mi++)
#pragma unroll
                for (int ni = 0; ni < 8; ni++)
                    mma_tf32(acc[mi][ni], a[mi], b[ni]);
        }
    };

    loadP(0);
    storeP(0);
    __syncthreads();
    for (int p = 0; p < NP; p++) {
        if (p + 1 < NP) loadP((p + 1)*32);
        compute(p & 1);
        if (p + 1 < NP) storeP((p + 1) & 1);
        __syncthreads();
    }

    // ---- epilogue ----
#pragma unroll
    for (int mi = 0; mi < 2; mi++) {
        int r0 = m0 + wm*32 + mi*16 + g;
#pragma unroll
        for (int ni = 0; ni < 8; ni++) {
            int c0 = n0 + wn*64 + ni*8 + 2*t;
            float b0 = bias ? bias[c0] : 0.f;
            float b1 = bias ? bias[c0 + 1] : 0.f;
            float v0 = acc[mi][ni][0]*scale + b0;
            float v1 = acc[mi][ni][1]*scale + b1;
            float v2 = acc[mi][ni][2]*scale + b0;
            float v3 = acc[mi][ni][3]*scale + b1;
            if (resid) {
                v0 += resid[(long)r0*N + c0];
                v1 += resid[(long)r0*N + c0 + 1];
                v2 += resid[(long)(r0 + 8)*N + c0];
                v3 += resid[(long)(r0 + 8)*N + c0 + 1];
            }
            if (relu) {
                v0 = fmaxf(v0, 0.f); v1 = fmaxf(v1, 0.f);
                v2 = fmaxf(v2, 0.f); v3 = fmaxf(v3, 0.f);
            }
            C[(long)r0*N + c0]           = v0;
            C[(long)r0*N + c0 + 1]       = v1;
            C[(long)(r0 + 8)*N + c0]     = v2;
            C[(long)(r0 + 8)*N + c0 + 1] = v3;
        }
    }
}

// ============ tf32 tensor-core GEMM NT: C[m,n] = A[m,:]·Bt[n,:] + bias[n] ============
__global__ void __launch_bounds__(256)
k_gemm_nt_tc(const float* __restrict__ A, const float* __restrict__ Bt,
             const float* __restrict__ bias, float* __restrict__ C,
             int M, int N, int K) {
    extern __shared__ float smem[];
    float* AsF = smem;                  // [2][128][36]
    float* BsF = smem + 2*128*36;       // [2][128][36]  (n-major)

    const int tid = threadIdx.x;
    const int m0 = blockIdx.y * 128;
    const int n0 = blockIdx.x * 128;
    const int lane = tid & 31, wid = tid >> 5;
    const int wm = wid & 3, wn = wid >> 2;
    const int g = lane >> 2, t = lane & 3;

    float acc[2][8][4];
#pragma unroll
    for (int mi = 0; mi < 2; mi++)
#pragma unroll
        for (int ni = 0; ni < 8; ni++)
#pragma unroll
            for (int j = 0; j < 4; j++) acc[mi][ni][j] = 0.f;

    float4 areg[4], breg[4];
    const int ar = tid >> 3;
    const int ac4 = (tid & 7) * 4;
    const int NP = K / 32;

    auto loadP = [&](int k0) {
#pragma unroll
        for (int i = 0; i < 4; i++)
            areg[i] = *(const float4*)&A[(long)(m0 + ar + i*32)*K + k0 + ac4];
#pragma unroll
        for (int i = 0; i < 4; i++)
            breg[i] = *(const float4*)&Bt[(long)(n0 + ar + i*32)*K + k0 + ac4];
    };

    auto storeP = [&](int buf) {
        float* As = AsF + buf*128*36;
        float* Bs = BsF + buf*128*36;
#pragma unroll
        for (int i = 0; i < 4; i++) {
            uint4 v;
            v.x = f2tf(areg[i].x); v.y = f2tf(areg[i].y);
            v.z = f2tf(areg[i].z); v.w = f2tf(areg[i].w);
            *(uint4*)&As[(ar + i*32)*36 + ac4] = v;
        }
#pragma unroll
        for (int i = 0; i < 4; i++) {
            uint4 v;
            v.x = f2tf(breg[i].x); v.y = f2tf(breg[i].y);
            v.z = f2tf(breg[i].z); v.w = f2tf(breg[i].w);
            *(uint4*)&Bs[(ar + i*32)*36 + ac4] = v;
        }
    };

    auto compute = [&](int buf) {
        const unsigned* As = (const unsigned*)(AsF + buf*128*36);
        const unsigned* Bs = (const unsigned*)(BsF + buf*128*36);
#pragma unroll
        for (int ks = 0; ks < 4; ks++) {
            int kk = ks*8;
            unsigned a[2][4];
#pragma unroll
            for (int mi = 0; mi < 2; mi++) {
                int row = wm*32 + mi*16 + g;
                a[mi][0] = As[row*36 + kk + t];
                a[mi][1] = As[(row + 8)*36 + kk + t];
                a[mi][2] = As[row*36 + kk + t + 4];
                a[mi][3] = As[(row + 8)*36 + kk + t + 4];
            }
            unsigned b[8][2];
#pragma unroll
            for (int ni = 0; ni < 8; ni++) {
                int col = wn*64 + ni*8 + g;
                b[ni][0] = Bs[col*36 + kk + t];
                b[ni][1] = Bs[col*36 + kk + t + 4];
            }
#pragma unroll
            for (int mi = 0; mi < 2; mi++)
#pragma unroll
                for (int ni = 0; ni < 8; ni++)
                    mma_tf32(acc[mi][ni], a[mi], b[ni]);
        }
    };

    loadP(0);
    storeP(0);
    __syncthreads();
    for (int p = 0; p < NP; p++) {
        if (p + 1 < NP) loadP((p + 1)*32);
        compute(p & 1);
        if (p + 1 < NP) storeP((p + 1) & 1);
        __syncthreads();
    }

#pragma unroll
    for (int mi = 0; mi < 2; mi++) {
        int r0 = m0 + wm*32 + mi*16 + g;
#pragma unroll
        for (int ni = 0; ni < 8; ni++) {
            int c0 = n0 + wn*64 + ni*8 + 2*t;
            float b0 = bias[c0], b1 = bias[c0 + 1];
            C[(long)r0*N + c0]           = acc[mi][ni][0] + b0;
            C[(long)r0*N + c0 + 1]       = acc[mi][ni][1] + b1;
            C[(long)(r0 + 8)*N + c0]     = acc[mi][ni][2] + b0;
            C[(long)(r0 + 8)*N + c0 + 1] = acc[mi][ni][3] + b1;
        }
    }
}

// ---------------- ACT step pieces ----------------
__global__ void k_active_chk() {
    __shared__ int any;
    if (threadIdx.x == 0) any = 0;
    __syncthreads();
    int loc = 0;
    for (int i = threadIdx.x; i < BL; i += blockDim.x)
        if (g_hp[i] < THRESHV && g_nu[i] < (float)NLMAX) loc = 1;
    if (loc) atomicOr(&any, 1);
    __syncthreads();
    if (threadIdx.x == 0) g_active = any;
}

__global__ void k_builds(int t, const float* __restrict__ pw, const float* __restrict__ pb) {
    if (!g_active) return;
    int row = blockIdx.x;
    int l = row % LQ;
    float dot = 0.f;
    for (int c = threadIdx.x; c < HD; c += blockDim.x) {
        float v = g_state[row*HD + c] + g_tsig[l*HD + c] + g_psig[t*HD + c];
        g_s[row*HD + c] = v;
        dot += v * pw[c];
    }
    float tot = blockReduceSum(dot);
    if (threadIdx.x == 0)
        g_pr[row] = 1.f / (1.f + expf(-(tot + pb[0])));
}

__global__ void k_ln(const float* __restrict__ X, const float* __restrict__ g,
                     const float* __restrict__ b, float* __restrict__ Y) {
    if (!g_active) return;
    int row = blockIdx.x;
    const float* x = X + row*HD;
    float s = 0.f;
    for (int c = threadIdx.x; c < HD; c += blockDim.x) s += x[c];
    float mu = blockReduceSum(s) / (float)HD;
    float vs = 0.f;
    for (int c = threadIdx.x; c < HD; c += blockDim.x) {
        float d = x[c] - mu; vs += d*d;
    }
    float var = blockReduceSum(vs) / (float)(HD - 1);
    float inv = 1.f / (sqrtf(var) + EPSV);
    for (int c = threadIdx.x; c < HD; c += blockDim.x)
        Y[row*HD + c] = g[c]*(x[c] - mu)*inv + b[c];
}

__global__ void k_attn() {
    if (!g_active) return;
    int bh = blockIdx.x;
    int b = bh / NHEAD, h = bh % NHEAD;
    __shared__ float ks[LQ*65];
    __shared__ float vs[LQ*65];
    __shared__ float qrow[4][DKH];
    __shared__ float ps[4][LQ + 1];
    int tid = threadIdx.x;
    long base = (long)(b*LQ)*HD + h*DKH;
    for (int i = tid; i < LQ*DKH; i += 128) {
        int j = i / DKH, d = i % DKH;
        ks[j*65 + d] = g_k[base + (long)j*HD + d];
        vs[j*65 + d] = g_v[base + (long)j*HD + d];
    }
    __syncthreads();
    int w = tid >> 5, lane = tid & 31;
    for (int r = w; r < LQ; r += 4) {
        for (int d = lane; d < DKH; d += 32) qrow[w][d] = g_q[base + (long)r*HD + d];
        __syncwarp();
        float sc[3];
#pragma unroll
        for (int jj = 0; jj < 3; jj++) {
            int j = lane + jj*32;
            float a = -3.0e38f;
            if (j < LQ) {
                a = 0.f;
#pragma unroll
                for (int d = 0; d < DKH; d++) a += qrow[w][d]*ks[j*65 + d];
            }
            sc[jj] = a;
        }
        float mx = fmaxf(sc[0], fmaxf(sc[1], sc[2]));
#pragma unroll
        for (int o = 16; o; o >>= 1) mx = fmaxf(mx, __shfl_xor_sync(0xffffffffu, mx, o));
        float sum = 0.f;
#pragma unroll
        for (int jj = 0; jj < 3; jj++) {
            int j = lane + jj*32;
            float e = (j < LQ) ? expf(sc[jj] - mx) : 0.f;
            sc[jj] = e; sum += e;
        }
#pragma unroll
        for (int o = 16; o; o >>= 1) sum += __shfl_xor_sync(0xffffffffu, sum, o);
        float inv = 1.f / sum;
#pragma unroll
        for (int jj = 0; jj < 3; jj++) {
            int j = lane + jj*32;
            if (j < LQ) ps[w][j] = sc[jj]*inv;
        }
        __syncwarp();
        for (int d = lane; d < DKH; d += 32) {
            float a = 0.f;
#pragma unroll 8
            for (int j = 0; j < LQ; j++) a += ps[w][j]*vs[j*65 + d];
            g_ctx[base + (long)r*HD + d] = a;
        }
        __syncwarp();
    }
}

__global__ void k_halt() {
    if (!g_active) return;
    int row = blockIdx.x;
    __shared__ float s_uw;
    if (threadIdx.x == 0) {
        float pr = g_pr[row], hp = g_hp[row], rem = g_rem[row], nu = g_nu[row];
        float still = (hp < 1.0f) ? 1.f : 0.f;
        float tot = hp + pr*still;
        float nh  = ((tot > THRESHV) ? 1.f : 0.f)*still;
        float st2 = ((tot <= THRESHV) ? 1.f : 0.f)*still;
        float hp2 = hp + pr*st2;
        float rem2 = rem + nh*(1.f - hp2);
        hp2 = hp2 + nh*rem2;
        float nu2 = nu + st2 + nh;
        float uw = pr*st2 + nh*rem2;
        g_hp[row] = hp2; g_rem[row] = rem2; g_nu[row] = nu2;
        s_uw = uw;
    }
    __syncthreads();
    float uw = s_uw;
    for (int c = threadIdx.x; c < HD; c += blockDim.x) {
        int i = row*HD + c;
        float y = g_y[i];
        g_prev[i]  = y*uw + g_prev[i]*(1.f - uw);
        g_state[i] = y;
    }
}

// ---------------- pooling / softmax / tail ----------------
__global__ void k_pool() {
    int b = blockIdx.x;
    for (int c = threadIdx.x; c < HD; c += blockDim.x) {
        float a = 0.f;
        for (int l = 0; l < LQ; l++) a += g_prev[(b*LQ + l)*HD + c];
        g_pooled[b*HD + c] = a / (float)LQ;
    }
}

__global__ void k_softmax(float* __restrict__ out) {
    int b = blockIdx.x;
    const float* a = out + (long)b*VOC;
    float* sm = out + (long)BB*VOC + (long)b*VOC;
    float mx = -3.0e38f;
    for (int i = threadIdx.x; i < VOC; i += blockDim.x) mx = fmaxf(mx, a[i]);
    float M = blockReduceMax(mx);
    float s = 0.f;
    for (int i = threadIdx.x; i < VOC; i += blockDim.x) s += expf(a[i] - M);
    float S = blockReduceSum(s);
    float inv = 1.f / S;
    for (int i = threadIdx.x; i < VOC; i += blockDim.x) sm[i] = expf(a[i] - M)*inv;
}

__global__ void k_tail(float* __restrict__ out) {
    int i = blockIdx.x * blockDim.x + threadIdx.x;
    if (i < BL) {
        out[(long)2*BB*VOC + i]      = g_rem[i];
        out[(long)2*BB*VOC + BL + i] = g_nu[i];
    }
}

// ---------------- host ----------------
extern "C" void kernel_launch(void* const* d_in, const int* in_sizes, int n_in,
                              void* d_out, int out_size) {
    const int*   story = (const int*)d_in[0];
    const int*   query = (const int*)d_in[1];
    const float* emb   = (const float*)d_in[2];
    const float* mask  = (const float*)d_in[3];
    const float* projw = (const float*)d_in[4];
    const float* ln1g  = (const float*)d_in[5];
    const float* ln1b  = (const float*)d_in[6];
    const float* wq    = (const float*)d_in[7];
    const float* wk    = (const float*)d_in[8];
    const float* wv    = (const float*)d_in[9];
    const float* wo    = (const float*)d_in[10];
    const float* c1w   = (const float*)d_in[11];
    const float* c1b   = (const float*)d_in[12];
    const float* c2w   = (const float*)d_in[13];
    const float* c2b   = (const float*)d_in[14];
    const float* ln2g  = (const float*)d_in[15];
    const float* ln2b  = (const float*)d_in[16];
    const float* pw    = (const float*)d_in[17];
    const float* pb    = (const float*)d_in[18];
    const float* outb  = (const float*)d_in[19];
    float* out = (float*)d_out;

    void *p_x, *p_state, *p_s, *p_xn, *p_q, *p_k, *p_v, *p_ctx, *p_s2, *p_xn2,
         *p_y, *p_mid, *p_w1t, *p_w2t, *p_pooled;
    cudaGetSymbolAddress(&p_x, g_x);
    cudaGetSymbolAddress(&p_state, g_state);
    cudaGetSymbolAddress(&p_s, g_s);
    cudaGetSymbolAddress(&p_xn, g_xn);
    cudaGetSymbolAddress(&p_q, g_q);
    cudaGetSymbolAddress(&p_k, g_k);
    cudaGetSymbolAddress(&p_v, g_v);
    cudaGetSymbolAddress(&p_ctx, g_ctx);
    cudaGetSymbolAddress(&p_s2, g_s2);
    cudaGetSymbolAddress(&p_xn2, g_xn2);
    cudaGetSymbolAddress(&p_y, g_y);
    cudaGetSymbolAddress(&p_mid, g_mid);
    cudaGetSymbolAddress(&p_w1t, g_w1t);
    cudaGetSymbolAddress(&p_w2t, g_w2t);
    cudaGetSymbolAddress(&p_pooled, g_pooled);

    cudaFuncSetAttribute(k_gemm_tc, cudaFuncAttributeMaxDynamicSharedMemorySize, SMEM_BYTES);
    cudaFuncSetAttribute(k_gemm_nt_tc, cudaFuncAttributeMaxDynamicSharedMemorySize, SMEM_BYTES);

    k_sigs<<<(LQ*HD + NLMAX*HD + 255)/256, 256>>>();
    k_wt1<<<(3*HD*FSZ + 255)/256, 256>>>(c1w);
    k_wt2<<<(3*FSZ*HD + 255)/256, 256>>>(c2w);
    k_init<<<(BL*HD + 255)/256, 256>>>();
    k_embed<<<BL, 128>>>(story, query, emb, mask);

    // state = x @ proj_w
    {
        dim3 grid(HD/128, BL/128);
        k_gemm_tc<<<grid, 256, SMEM_BYTES>>>((const float*)p_x, projw, (float*)p_state,
                                             BL, HD, HD, nullptr, nullptr, 1.f, 0, 0, 0, 0, 0);
    }

    for (int t = 0; t < NLMAX; t++) {
        k_active_chk<<<1, 1024>>>();
        k_builds<<<BL, 256>>>(t, pw, pb);
        k_ln<<<BL, 256>>>((const float*)p_s, ln1g, ln1b, (float*)p_xn);
        dim3 g512(HD/128, BL/128);
        k_gemm_tc<<<g512, 256, SMEM_BYTES>>>((const float*)p_xn, wq, (float*)p_q, BL, HD, HD,
                                             nullptr, nullptr, 0.125f, 0, 1, 0, 0, 0);
        k_gemm_tc<<<g512, 256, SMEM_BYTES>>>((const float*)p_xn, wk, (float*)p_k, BL, HD, HD,
                                             nullptr, nullptr, 1.f, 0, 1, 0, 0, 0);
        k_gemm_tc<<<g512, 256, SMEM_BYTES>>>((const float*)p_xn, wv, (float*)p_v, BL, HD, HD,
                                             nullptr, nullptr, 1.f, 0, 1, 0, 0, 0);
        k_attn<<<BB*NHEAD, 128>>>();
        k_gemm_tc<<<g512, 256, SMEM_BYTES>>>((const float*)p_ctx, wo, (float*)p_s2, BL, HD, HD,
                                             nullptr, (const float*)p_s, 1.f, 0, 1, 0, 0, 0);
        k_ln<<<BL, 256>>>((const float*)p_s2, ln2g, ln2b, (float*)p_xn2);
        dim3 gc1(FSZ/128, BL/128);
        k_gemm_tc<<<gc1, 256, SMEM_BYTES>>>((const float*)p_xn2, (const float*)p_w1t, (float*)p_mid,
                                            BL, FSZ, 3*HD, c1b, nullptr, 1.f, 1, 1, 1, HD, 9);
        dim3 gc2(HD/128, BL/128);
        k_gemm_tc<<<gc2, 256, SMEM_BYTES>>>((const float*)p_mid, (const float*)p_w2t, (float*)p_y,
                                            BL, HD, 3*FSZ, c2b, (const float*)p_s2, 1.f, 0, 1, 1, FSZ, 11);
        k_halt<<<BL, 256>>>();
    }

    k_pool<<<BB, 256>>>();
    {
        dim3 grid(VOC/128, BB/128);
        k_gemm_nt_tc<<<grid, 256, SMEM_BYTES>>>((const float*)p_pooled, emb, outb, out, BB, VOC, HD);
    }
    k_softmax<<<BB, 1024>>>(out);
    k_tail<<<(BL + 255)/256, 256>>>(out);
}

// round 6
// speedup vs baseline: 3.7187x; 1.4841x over previous
#include <cuda_runtime.h>
#include <math.h>

#define BB     256
#define MEMN   70
#define SLENQ  11
#define LQ     71
#define BL     (BB*LQ)       // 18176
#define HD     512
#define FSZ    2048
#define NHEAD  8
#define DKH    64
#define NLMAX  6
#define VOC    32000
#define THRESHV 0.9f
#define EPSV   1e-6f

// smem stage sizes (floats)
#define ASZ (128*36)
#define BSZ (32*136)
#define BSZ_NT (128*36)
#define SMEM_NN (3*(ASZ+BSZ)*4)      // 107520 B
#define SMEM_NT (3*(ASZ+BSZ_NT)*4)   // 110592 B

// ---------------- scratch (device globals; no allocation) ----------------
__device__ float g_x[BL*HD];
__device__ float g_state[BL*HD];
__device__ float g_prev[BL*HD];
__device__ float g_s[BL*HD];
__device__ float g_xn[BL*HD];
__device__ float g_q[BL*HD];
__device__ float g_k[BL*HD];
__device__ float g_v[BL*HD];
__device__ float g_ctx[BL*HD];
__device__ float g_s2[BL*HD];
__device__ float g_xn2[BL*HD];
__device__ float g_y[BL*HD];
__device__ float g_mid[BL*FSZ];
__device__ float g_w1t[3*HD*FSZ];        // [3*512][2048]  (tf32-rounded)
__device__ float g_w2t[3*FSZ*HD];        // [3*2048][512]  (tf32-rounded)
__device__ float g_wr[5*HD*HD];          // rounded projw,wq,wk,wv,wo
__device__ float g_embr[VOC*HD];         // rounded emb
__device__ float g_tsig[LQ*HD];
__device__ float g_psig[NLMAX*HD];
__device__ float g_hp[BL], g_rem[BL], g_nu[BL], g_pr[BL];
__device__ float g_pooled[BB*HD];
__device__ int   g_active;

// ---------------- helpers ----------------
__device__ __forceinline__ float roundtf(float f) {
    unsigned u;
    asm("cvt.rna.tf32.f32 %0, %1;" : "=r"(u) : "f"(f));
    return __uint_as_float(u);
}

__device__ __forceinline__ void mma_tf32(float* d, const unsigned* a, const unsigned* b) {
    asm volatile(
        "mma.sync.aligned.m16n8k8.row.col.f32.tf32.tf32.f32 "
        "{%0,%1,%2,%3}, {%4,%5,%6,%7}, {%8,%9}, {%0,%1,%2,%3};"
        : "+f"(d[0]), "+f"(d[1]), "+f"(d[2]), "+f"(d[3])
        : "r"(a[0]), "r"(a[1]), "r"(a[2]), "r"(a[3]), "r"(b[0]), "r"(b[1]));
}

__device__ __forceinline__ void cp16(void* dst, const void* src, int ss) {
    unsigned d = (unsigned)__cvta_generic_to_shared(dst);
    asm volatile("cp.async.cg.shared.global [%0], [%1], 16, %2;"
                 :: "r"(d), "l"(src), "r"(ss));
}
__device__ __forceinline__ void cp_commit() {
    asm volatile("cp.async.commit_group;");
}
__device__ __forceinline__ void cp_wait1() {
    asm volatile("cp.async.wait_group 1;");
}

__device__ __forceinline__ float blockReduceSum(float v) {
    __shared__ float sh[32];
    __shared__ float res;
    int lane = threadIdx.x & 31, wid = threadIdx.x >> 5;
#pragma unroll
    for (int o = 16; o; o >>= 1) v += __shfl_xor_sync(0xffffffffu, v, o);
    if (lane == 0) sh[wid] = v;
    __syncthreads();
    if (wid == 0) {
        float x = (lane < (int)(blockDim.x >> 5)) ? sh[lane] : 0.f;
#pragma unroll
        for (int o = 16; o; o >>= 1) x += __shfl_xor_sync(0xffffffffu, x, o);
        if (lane == 0) res = x;
    }
    __syncthreads();
    return res;
}

__device__ __forceinline__ float blockReduceMax(float v) {
    __shared__ float sh[32];
    __shared__ float res;
    int lane = threadIdx.x & 31, wid = threadIdx.x >> 5;
#pragma unroll
    for (int o = 16; o; o >>= 1) v = fmaxf(v, __shfl_xor_sync(0xffffffffu, v, o));
    if (lane == 0) sh[wid] = v;
    __syncthreads();
    if (wid == 0) {
        float x = (lane < (int)(blockDim.x >> 5)) ? sh[lane] : -3.0e38f;
#pragma unroll
        for (int o = 16; o; o >>= 1) x = fmaxf(x, __shfl_xor_sync(0xffffffffu, x, o));
        if (lane == 0) res = x;
    }
    __syncthreads();
    return res;
}

// ---------------- init / signals / weight prep ----------------
__global__ void k_init() {
    int i = blockIdx.x * blockDim.x + threadIdx.x;
    if (i < BL*HD) g_prev[i] = 0.f;
    if (i < BL) { g_hp[i] = 0.f; g_rem[i] = 0.f; g_nu[i] = 0.f; }
}

__global__ void k_sigs() {
    int i = blockIdx.x * blockDim.x + threadIdx.x;
    const float log_inc = logf(1e4f) / 255.f;
    if (i < LQ*HD) {
        int pos = i / HD, c = i % HD;
        int j = (c < 256) ? c : c - 256;
        float val = (float)pos * expf(-log_inc * (float)j);
        g_tsig[i] = (c < 256) ? sinf(val) : cosf(val);
    } else {
        int k = i - LQ*HD;
        if (k < NLMAX*HD) {
            int pos = k / HD, c = k % HD;
            int j = (c < 256) ? c : c - 256;
            float val = (float)pos * expf(-log_inc * (float)j);
            g_psig[k] = (c < 256) ? sinf(val) : cosf(val);
        }
    }
}

__global__ void k_wt1(const float* __restrict__ w) {
    int i = blockIdx.x * blockDim.x + threadIdx.x;
    if (i < 3*HD*FSZ) {
        int f = i % FSZ;
        int rest = i / FSZ;
        int kk = rest / HD, c = rest % HD;
        g_w1t[i] = roundtf(w[(f*HD + c)*3 + kk]);
    }
}

__global__ void k_wt2(const float* __restrict__ w) {
    int i = blockIdx.x * blockDim.x + threadIdx.x;
    if (i < 3*FSZ*HD) {
        int f = i % HD;
        int rest = i / HD;
        int kk = rest / FSZ, c = rest % FSZ;
        g_w2t[i] = roundtf(w[(f*FSZ + c)*3 + kk]);
    }
}

__global__ void k_roundw(const float* __restrict__ projw, const float* __restrict__ wq,
                         const float* __restrict__ wk, const float* __restrict__ wv,
                         const float* __restrict__ wo) {
    int i = blockIdx.x * blockDim.x + threadIdx.x;
    if (i < HD*HD) {
        g_wr[0*HD*HD + i] = roundtf(projw[i]);
        g_wr[1*HD*HD + i] = roundtf(wq[i]);
        g_wr[2*HD*HD + i] = roundtf(wk[i]);
        g_wr[3*HD*HD + i] = roundtf(wv[i]);
        g_wr[4*HD*HD + i] = roundtf(wo[i]);
    }
}

__global__ void k_rounde(const float* __restrict__ emb) {
    long i = (long)blockIdx.x * blockDim.x + threadIdx.x;
    if (i < (long)VOC*HD) g_embr[i] = roundtf(emb[i]);
}

// ---------------- embedding (output rounded: feeds proj GEMM) ----------------
__global__ void k_embed(const int* __restrict__ story, const int* __restrict__ query,
                        const float* __restrict__ emb, const float* __restrict__ mask) {
    int row = blockIdx.x;
    int b = row / LQ, m = row % LQ;
    for (int c = threadIdx.x; c < HD; c += blockDim.x) {
        float acc = 0.f;
        if (m < MEMN) {
#pragma unroll
            for (int s = 0; s < SLENQ; s++) {
                int tok = story[(b*MEMN + m)*SLENQ + s];
                acc += emb[(long)tok*HD + c] * mask[s*HD + c];
            }
        } else {
#pragma unroll
            for (int s = 0; s < SLENQ; s++) {
                int tok = query[b*SLENQ + s];
                acc += emb[(long)tok*HD + c] * mask[s*HD + c];
            }
        }
        g_x[row*HD + c] = roundtf(acc);
    }
}

// ============ tf32 tensor-core GEMM, cp.async 3-stage (NN + conv-im2col) ============
// C = act(scale * A@W + bias + resid); operands MUST be pre-rounded to tf32.
__global__ void __launch_bounds__(256)
k_gemm_tc(const float* __restrict__ A, const float* __restrict__ W,
          float* __restrict__ C, int M, int N, int K,
          const float* __restrict__ bias, const float* __restrict__ resid,
          float scale, int relu, int chk, int conv, int Cin, int cshift, int rnd) {
    if (chk && !g_active) return;
    extern __shared__ float smem[];
    float* AsF = smem;                   // [3][128][36]
    float* BsF = smem + 3*ASZ;           // [3][32][136]

    const int tid = threadIdx.x;
    const int m0 = blockIdx.y * 128;
    const int n0 = blockIdx.x * 128;
    const int lane = tid & 31, wid = tid >> 5;
    const int wm = wid & 3, wn = wid >> 2;
    const int g = lane >> 2, t = lane & 3;

    float acc[2][8][4];
#pragma unroll
    for (int mi = 0; mi < 2; mi++)
#pragma unroll
        for (int ni = 0; ni < 8; ni++)
#pragma unroll
            for (int j = 0; j < 4; j++) acc[mi][ni][j] = 0.f;

    const int ar = tid >> 3;            // 0..31
    const int ac4 = (tid & 7) * 4;      // 0,4,..,28
    const int br = tid >> 5;            // 0..7
    const int bc4 = (tid & 31) * 4;     // 0..124
    const int NP = K / 32;

    auto loadP = [&](int k0, int buf) {
        float* As = AsF + buf*ASZ;
        float* Bs = BsF + buf*BSZ;
        if (conv) {
            int kk = k0 >> cshift;
            int cb = k0 & (Cin - 1);
#pragma unroll
            for (int i = 0; i < 4; i++) {
                int m = m0 + ar + i*32;
                int b = m / LQ, l = m - b*LQ;
                int lp = l + kk - 1;
                int ok = (lp >= 0 && lp < LQ);
                const float* src = &A[(long)(b*LQ + (ok ? lp : 0))*Cin + cb + ac4];
                cp16(&As[(ar + i*32)*36 + ac4], src, ok ? 16 : 0);
            }
        } else {
#pragma unroll
            for (int i = 0; i < 4; i++)
                cp16(&As[(ar + i*32)*36 + ac4],
                     &A[(long)(m0 + ar + i*32)*K + k0 + ac4], 16);
        }
#pragma unroll
        for (int i = 0; i < 4; i++)
            cp16(&Bs[(br + i*8)*136 + bc4],
                 &W[(long)(k0 + br + i*8)*N + n0 + bc4], 16);
    };

    auto compute = [&](int buf) {
        const unsigned* As = (const unsigned*)(AsF + buf*ASZ);
        const unsigned* Bs = (const unsigned*)(BsF + buf*BSZ);
#pragma unroll
        for (int ks = 0; ks < 4; ks++) {
            int kk = ks*8;
            unsigned a[2][4];
#pragma unroll
            for (int mi = 0; mi < 2; mi++) {
                int row = wm*32 + mi*16 + g;
                a[mi][0] = As[row*36 + kk + t];
                a[mi][1] = As[(row + 8)*36 + kk + t];
                a[mi][2] = As[row*36 + kk + t + 4];
                a[mi][3] = As[(row + 8)*36 + kk + t + 4];
            }
            unsigned b[8][2];
#pragma unroll
            for (int ni = 0; ni < 8; ni++) {
                int col = wn*64 + ni*8 + g;
                b[ni][0] = Bs[(kk + t)*136 + col];
                b[ni][1] = Bs[(kk + t + 4)*136 + col];
            }
#pragma unroll
            for (int mi = 0; mi < 2; mi++)
#pragma unroll
                for (int ni = 0; ni < 8; ni++)
                    mma_tf32(acc[mi][ni], a[mi], b[ni]);
        }
    };

    loadP(0, 0);
    cp_commit();
    if (NP > 1) loadP(32, 1);
    cp_commit();

    for (int p = 0; p < NP; p++) {
        cp_wait1();
        __syncthreads();
        int pn = p + 2;
        if (pn < NP) loadP(pn*32, pn % 3);
        cp_commit();
        compute(p % 3);
    }

    // ---- epilogue ----
#pragma unroll
    for (int mi = 0; mi < 2; mi++) {
        int r0 = m0 + wm*32 + mi*16 + g;
#pragma unroll
        for (int ni = 0; ni < 8; ni++) {
            int c0 = n0 + wn*64 + ni*8 + 2*t;
            float b0 = bias ? bias[c0] : 0.f;
            float b1 = bias ? bias[c0 + 1] : 0.f;
            float v0 = acc[mi][ni][0]*scale + b0;
            float v1 = acc[mi][ni][1]*scale + b1;
            float v2 = acc[mi][ni][2]*scale + b0;
            float v3 = acc[mi][ni][3]*scale + b1;
            if (resid) {
                v0 += resid[(long)r0*N + c0];
                v1 += resid[(long)r0*N + c0 + 1];
                v2 += resid[(long)(r0 + 8)*N + c0];
                v3 += resid[(long)(r0 + 8)*N + c0 + 1];
            }
            if (relu) {
                v0 = fmaxf(v0, 0.f); v1 = fmaxf(v1, 0.f);
                v2 = fmaxf(v2, 0.f); v3 = fmaxf(v3, 0.f);
            }
            if (rnd) {
                v0 = roundtf(v0); v1 = roundtf(v1);
                v2 = roundtf(v2); v3 = roundtf(v3);
            }
            C[(long)r0*N + c0]           = v0;
            C[(long)r0*N + c0 + 1]       = v1;
            C[(long)(r0 + 8)*N + c0]     = v2;
            C[(long)(r0 + 8)*N + c0 + 1] = v3;
        }
    }
}

// ============ tf32 GEMM NT, cp.async 3-stage: C = A·Bt^T + bias ============
__global__ void __launch_bounds__(256)
k_gemm_nt_tc(const float* __restrict__ A, const float* __restrict__ Bt,
             const float* __restrict__ bias, float* __restrict__ C,
             int M, int N, int K) {
    extern __shared__ float smem[];
    float* AsF = smem;                   // [3][128][36]
    float* BsF = smem + 3*ASZ;           // [3][128][36]  n-major

    const int tid = threadIdx.x;
    const int m0 = blockIdx.y * 128;
    const int n0 = blockIdx.x * 128;
    const int lane = tid & 31, wid = tid >> 5;
    const int wm = wid & 3, wn = wid >> 2;
    const int g = lane >> 2, t = lane & 3;

    float acc[2][8][4];
#pragma unroll
    for (int mi = 0; mi < 2; mi++)
#pragma unroll
        for (int ni = 0; ni < 8; ni++)
#pragma unroll
            for (int j = 0; j < 4; j++) acc[mi][ni][j] = 0.f;

    const int ar = tid >> 3;
    const int ac4 = (tid & 7) * 4;
    const int NP = K / 32;

    auto loadP = [&](int k0, int buf) {
        float* As = AsF + buf*ASZ;
        float* Bs = BsF + buf*BSZ_NT;
#pragma unroll
        for (int i = 0; i < 4; i++)
            cp16(&As[(ar + i*32)*36 + ac4],
                 &A[(long)(m0 + ar + i*32)*K + k0 + ac4], 16);
#pragma unroll
        for (int i = 0; i < 4; i++)
            cp16(&Bs[(ar + i*32)*36 + ac4],
                 &Bt[(long)(n0 + ar + i*32)*K + k0 + ac4], 16);
    };

    auto compute = [&](int buf) {
        const unsigned* As = (const unsigned*)(AsF + buf*ASZ);
        const unsigned* Bs = (const unsigned*)(BsF + buf*BSZ_NT);
#pragma unroll
        for (int ks = 0; ks < 4; ks++) {
            int kk = ks*8;
            unsigned a[2][4];
#pragma unroll
            for (int mi = 0; mi < 2; mi++) {
                int row = wm*32 + mi*16 + g;
                a[mi][0] = As[row*36 + kk + t];
                a[mi][1] = As[(row + 8)*36 + kk + t];
                a[mi][2] = As[row*36 + kk + t + 4];
                a[mi][3] = As[(row + 8)*36 + kk + t + 4];
            }
            unsigned b[8][2];
#pragma unroll
            for (int ni = 0; ni < 8; ni++) {
                int col = wn*64 + ni*8 + g;
                b[ni][0] = Bs[col*36 + kk + t];
                b[ni][1] = Bs[col*36 + kk + t + 4];
            }
#pragma unroll
            for (int mi = 0; mi < 2; mi++)
#pragma unroll
                for (int ni = 0; ni < 8; ni++)
                    mma_tf32(acc[mi][ni], a[mi], b[ni]);
        }
    };

    loadP(0, 0);
    cp_commit();
    if (NP > 1) loadP(32, 1);
    cp_commit();

    for (int p = 0; p < NP; p++) {
        cp_wait1();
        __syncthreads();
        int pn = p + 2;
        if (pn < NP) loadP(pn*32, pn % 3);
        cp_commit();
        compute(p % 3);
    }

#pragma unroll
    for (int mi = 0; mi < 2; mi++) {
        int r0 = m0 + wm*32 + mi*16 + g;
#pragma unroll
        for (int ni = 0; ni < 8; ni++) {
            int c0 = n0 + wn*64 + ni*8 + 2*t;
            float b0 = bias[c0], b1 = bias[c0 + 1];
            C[(long)r0*N + c0]           = acc[mi][ni][0] + b0;
            C[(long)r0*N + c0 + 1]       = acc[mi][ni][1] + b1;
            C[(long)(r0 + 8)*N + c0]     = acc[mi][ni][2] + b0;
            C[(long)(r0 + 8)*N + c0 + 1] = acc[mi][ni][3] + b1;
        }
    }
}

// ---------------- ACT step pieces ----------------
__global__ void k_active_chk() {
    __shared__ int any;
    if (threadIdx.x == 0) any = 0;
    __syncthreads();
    int loc = 0;
    for (int i = threadIdx.x; i < BL; i += blockDim.x)
        if (g_hp[i] < THRESHV && g_nu[i] < (float)NLMAX) loc = 1;
    if (loc) atomicOr(&any, 1);
    __syncthreads();
    if (threadIdx.x == 0) g_active = any;
}

// fused: build s, halting prob, LayerNorm1 -> xn (rounded)
__global__ void k_builds_ln(int t, const float* __restrict__ pw, const float* __restrict__ pb,
                            const float* __restrict__ lng, const float* __restrict__ lnb) {
    if (!g_active) return;
    int row = blockIdx.x;
    int l = row % LQ;
    int c0 = threadIdx.x, c1 = threadIdx.x + 256;
    float v0 = g_state[row*HD + c0] + g_tsig[l*HD + c0] + g_psig[t*HD + c0];
    float v1 = g_state[row*HD + c1] + g_tsig[l*HD + c1] + g_psig[t*HD + c1];
    g_s[row*HD + c0] = v0;
    g_s[row*HD + c1] = v1;
    float dot = v0*pw[c0] + v1*pw[c1];
    float tot = blockReduceSum(dot);
    if (threadIdx.x == 0)
        g_pr[row] = 1.f / (1.f + expf(-(tot + pb[0])));
    float mu = blockReduceSum(v0 + v1) / (float)HD;
    float d0 = v0 - mu, d1 = v1 - mu;
    float var = blockReduceSum(d0*d0 + d1*d1) / (float)(HD - 1);
    float inv = 1.f / (sqrtf(var) + EPSV);
    g_xn[row*HD + c0] = roundtf(lng[c0]*d0*inv + lnb[c0]);
    g_xn[row*HD + c1] = roundtf(lng[c1]*d1*inv + lnb[c1]);
}

__global__ void k_ln(const float* __restrict__ X, const float* __restrict__ g,
                     const float* __restrict__ b, float* __restrict__ Y) {
    if (!g_active) return;
    int row = blockIdx.x;
    const float* x = X + row*HD;
    float s = 0.f;
    for (int c = threadIdx.x; c < HD; c += blockDim.x) s += x[c];
    float mu = blockReduceSum(s) / (float)HD;
    float vs = 0.f;
    for (int c = threadIdx.x; c < HD; c += blockDim.x) {
        float d = x[c] - mu; vs += d*d;
    }
    float var = blockReduceSum(vs) / (float)(HD - 1);
    float inv = 1.f / (sqrtf(var) + EPSV);
    for (int c = threadIdx.x; c < HD; c += blockDim.x)
        Y[row*HD + c] = roundtf(g[c]*(x[c] - mu)*inv + b[c]);
}

__global__ void k_attn() {
    if (!g_active) return;
    int bh = blockIdx.x;
    int b = bh / NHEAD, h = bh % NHEAD;
    __shared__ float ks[LQ*65];
    __shared__ float vs[LQ*65];
    __shared__ float qrow[4][DKH];
    __shared__ float ps[4][LQ + 1];
    int tid = threadIdx.x;
    long base = (long)(b*LQ)*HD + h*DKH;
    for (int i = tid; i < LQ*DKH; i += 128) {
        int j = i / DKH, d = i % DKH;
        ks[j*65 + d] = g_k[base + (long)j*HD + d];
        vs[j*65 + d] = g_v[base + (long)j*HD + d];
    }
    __syncthreads();
    int w = tid >> 5, lane = tid & 31;
    for (int r = w; r < LQ; r += 4) {
        for (int d = lane; d < DKH; d += 32) qrow[w][d] = g_q[base + (long)r*HD + d];
        __syncwarp();
        float sc[3];
#pragma unroll
        for (int jj = 0; jj < 3; jj++) {
            int j = lane + jj*32;
            float a = -3.0e38f;
            if (j < LQ) {
                a = 0.f;
#pragma unroll
                for (int d = 0; d < DKH; d++) a += qrow[w][d]*ks[j*65 + d];
            }
            sc[jj] = a;
        }
        float mx = fmaxf(sc[0], fmaxf(sc[1], sc[2]));
#pragma unroll
        for (int o = 16; o; o >>= 1) mx = fmaxf(mx, __shfl_xor_sync(0xffffffffu, mx, o));
        float sum = 0.f;
#pragma unroll
        for (int jj = 0; jj < 3; jj++) {
            int j = lane + jj*32;
            float e = (j < LQ) ? expf(sc[jj] - mx) : 0.f;
            sc[jj] = e; sum += e;
        }
#pragma unroll
        for (int o = 16; o; o >>= 1) sum += __shfl_xor_sync(0xffffffffu, sum, o);
        float inv = 1.f / sum;
#pragma unroll
        for (int jj = 0; jj < 3; jj++) {
            int j = lane + jj*32;
            if (j < LQ) ps[w][j] = sc[jj]*inv;
        }
        __syncwarp();
        for (int d = lane; d < DKH; d += 32) {
            float a = 0.f;
#pragma unroll 8
            for (int j = 0; j < LQ; j++) a += ps[w][j]*vs[j*65 + d];
            g_ctx[base + (long)r*HD + d] = roundtf(a);
        }
        __syncwarp();
    }
}

__global__ void k_halt() {
    if (!g_active) return;
    int row = blockIdx.x;
    __shared__ float s_uw;
    if (threadIdx.x == 0) {
        float pr = g_pr[row], hp = g_hp[row], rem = g_rem[row], nu = g_nu[row];
        float still = (hp < 1.0f) ? 1.f : 0.f;
        float tot = hp + pr*still;
        float nh  = ((tot > THRESHV) ? 1.f : 0.f)*still;
        float st2 = ((tot <= THRESHV) ? 1.f : 0.f)*still;
        float hp2 = hp + pr*st2;
        float rem2 = rem + nh*(1.f - hp2);
        hp2 = hp2 + nh*rem2;
        float nu2 = nu + st2 + nh;
        float uw = pr*st2 + nh*rem2;
        g_hp[row] = hp2; g_rem[row] = rem2; g_nu[row] = nu2;
        s_uw = uw;
    }
    __syncthreads();
    float uw = s_uw;
    for (int c = threadIdx.x; c < HD; c += blockDim.x) {
        int i = row*HD + c;
        float y = g_y[i];
        g_prev[i]  = y*uw + g_prev[i]*(1.f - uw);
        g_state[i] = y;
    }
}

// ---------------- pooling / softmax / tail ----------------
__global__ void k_pool() {
    int b = blockIdx.x;
    for (int c = threadIdx.x; c < HD; c += blockDim.x) {
        float a = 0.f;
        for (int l = 0; l < LQ; l++) a += g_prev[(b*LQ + l)*HD + c];
        g_pooled[b*HD + c] = roundtf(a / (float)LQ);
    }
}

__global__ void k_softmax(float* __restrict__ out) {
    int b = blockIdx.x;
    const float* a = out + (long)b*VOC;
    float* sm = out + (long)BB*VOC + (long)b*VOC;
    float mx = -3.0e38f;
    for (int i = threadIdx.x; i < VOC; i += blockDim.x) mx = fmaxf(mx, a[i]);
    float M = blockReduceMax(mx);
    float s = 0.f;
    for (int i = threadIdx.x; i < VOC; i += blockDim.x) s += expf(a[i] - M);
    float S = blockReduceSum(s);
    float inv = 1.f / S;
    for (int i = threadIdx.x; i < VOC; i += blockDim.x) sm[i] = expf(a[i] - M)*inv;
}

__global__ void k_tail(float* __restrict__ out) {
    int i = blockIdx.x * blockDim.x + threadIdx.x;
    if (i < BL) {
        out[(long)2*BB*VOC + i]      = g_rem[i];
        out[(long)2*BB*VOC + BL + i] = g_nu[i];
    }
}

// ---------------- host ----------------
extern "C" void kernel_launch(void* const* d_in, const int* in_sizes, int n_in,
                              void* d_out, int out_size) {
    const int*   story = (const int*)d_in[0];
    const int*   query = (const int*)d_in[1];
    const float* emb   = (const float*)d_in[2];
    const float* mask  = (const float*)d_in[3];
    const float* projw = (const float*)d_in[4];
    const float* ln1g  = (const float*)d_in[5];
    const float* ln1b  = (const float*)d_in[6];
    const float* wq    = (const float*)d_in[7];
    const float* wk    = (const float*)d_in[8];
    const float* wv    = (const float*)d_in[9];
    const float* wo    = (const float*)d_in[10];
    const float* c1w   = (const float*)d_in[11];
    const float* c1b   = (const float*)d_in[12];
    const float* c2w   = (const float*)d_in[13];
    const float* c2b   = (const float*)d_in[14];
    const float* ln2g  = (const float*)d_in[15];
    const float* ln2b  = (const float*)d_in[16];
    const float* pw    = (const float*)d_in[17];
    const float* pb    = (const float*)d_in[18];
    const float* outb  = (const float*)d_in[19];
    float* out = (float*)d_out;

    void *p_x, *p_state, *p_s, *p_xn, *p_q, *p_k, *p_v, *p_ctx, *p_s2, *p_xn2,
         *p_y, *p_mid, *p_w1t, *p_w2t, *p_pooled, *p_wr, *p_embr;
    cudaGetSymbolAddress(&p_x, g_x);
    cudaGetSymbolAddress(&p_state, g_state);
    cudaGetSymbolAddress(&p_s, g_s);
    cudaGetSymbolAddress(&p_xn, g_xn);
    cudaGetSymbolAddress(&p_q, g_q);
    cudaGetSymbolAddress(&p_k, g_k);
    cudaGetSymbolAddress(&p_v, g_v);
    cudaGetSymbolAddress(&p_ctx, g_ctx);
    cudaGetSymbolAddress(&p_s2, g_s2);
    cudaGetSymbolAddress(&p_xn2, g_xn2);
    cudaGetSymbolAddress(&p_y, g_y);
    cudaGetSymbolAddress(&p_mid, g_mid);
    cudaGetSymbolAddress(&p_w1t, g_w1t);
    cudaGetSymbolAddress(&p_w2t, g_w2t);
    cudaGetSymbolAddress(&p_pooled, g_pooled);
    cudaGetSymbolAddress(&p_wr, g_wr);
    cudaGetSymbolAddress(&p_embr, g_embr);
    const float* wr = (const float*)p_wr;

    cudaFuncSetAttribute(k_gemm_tc, cudaFuncAttributeMaxDynamicSharedMemorySize, SMEM_NN);
    cudaFuncSetAttribute(k_gemm_nt_tc, cudaFuncAttributeMaxDynamicSharedMemorySize, SMEM_NT);

    k_sigs<<<(LQ*HD + NLMAX*HD + 255)/256, 256>>>();
    k_wt1<<<(3*HD*FSZ + 255)/256, 256>>>(c1w);
    k_wt2<<<(3*FSZ*HD + 255)/256, 256>>>(c2w);
    k_roundw<<<(HD*HD + 255)/256, 256>>>(projw, wq, wk, wv, wo);
    k_rounde<<<(VOC*HD + 255)/256, 256>>>(emb);
    k_init<<<(BL*HD + 255)/256, 256>>>();
    k_embed<<<BL, 128>>>(story, query, emb, mask);

    // state = x @ proj_w
    {
        dim3 grid(HD/128, BL/128);
        k_gemm_tc<<<grid, 256, SMEM_NN>>>((const float*)p_x, wr + 0*HD*HD, (float*)p_state,
                                          BL, HD, HD, nullptr, nullptr, 1.f, 0, 0, 0, 0, 0, 0);
    }

    for (int t = 0; t < NLMAX; t++) {
        k_active_chk<<<1, 1024>>>();
        k_builds_ln<<<BL, 256>>>(t, pw, pb, ln1g, ln1b);
        dim3 g512(HD/128, BL/128);
        k_gemm_tc<<<g512, 256, SMEM_NN>>>((const float*)p_xn, wr + 1*HD*HD, (float*)p_q, BL, HD, HD,
                                          nullptr, nullptr, 0.125f, 0, 1, 0, 0, 0, 0);
        k_gemm_tc<<<g512, 256, SMEM_NN>>>((const float*)p_xn, wr + 2*HD*HD, (float*)p_k, BL, HD, HD,
                                          nullptr, nullptr, 1.f, 0, 1, 0, 0, 0, 0);
        k_gemm_tc<<<g512, 256, SMEM_NN>>>((const float*)p_xn, wr + 3*HD*HD, (float*)p_v, BL, HD, HD,
                                          nullptr, nullptr, 1.f, 0, 1, 0, 0, 0, 0);
        k_attn<<<BB*NHEAD, 128>>>();
        k_gemm_tc<<<g512, 256, SMEM_NN>>>((const float*)p_ctx, wr + 4*HD*HD, (float*)p_s2, BL, HD, HD,
                                          nullptr, (const float*)p_s, 1.f, 0, 1, 0, 0, 0, 0);
        k_ln<<<BL, 256>>>((const float*)p_s2, ln2g, ln2b, (float*)p_xn2);
        dim3 gc1(FSZ/128, BL/128);
        k_gemm_tc<<<gc1, 256, SMEM_NN>>>((const float*)p_xn2, (const float*)p_w1t, (float*)p_mid,
                                         BL, FSZ, 3*HD, c1b, nullptr, 1.f, 1, 1, 1, HD, 9, 1);
        dim3 gc2(HD/128, BL/128);
        k_gemm_tc<<<gc2, 256, SMEM_NN>>>((const float*)p_mid, (const float*)p_w2t, (float*)p_y,
                                         BL, HD, 3*FSZ, c2b, (const float*)p_s2, 1.f, 0, 1, 1, FSZ, 11, 0);
        k_halt<<<BL, 256>>>();
    }

    k_pool<<<BB, 256>>>();
    {
        dim3 grid(VOC/128, BB/128);
        k_gemm_nt_tc<<<grid, 256, SMEM_NT>>>((const float*)p_pooled, (const float*)p_embr,
                                             outb, out, BB, VOC, HD);
    }
    k_softmax<<<BB, 1024>>>(out);
    k_tail<<<(BL + 255)/256, 256>>>(out);
}